// round 15
// baseline (speedup 1.0000x reference)
#include <cuda_runtime.h>
#include <cuda_fp16.h>
#include <mma.h>
#include <cstdint>

using namespace nvcuda;

// Problem constants (fixed by the dataset)
static constexpr int NN = 50000;   // nodes
static constexpr int NE = 800000;  // edges (divisible by 4)
// features: 128 -> 128 (hidden) -> 64 (out)

// scan decomposition
static constexpr int SCAN_T = 1024;
static constexpr int CHUNK  = 52;          // 1024*52 = 53248 >= NN

// persistent prep kernel geometry (2 CTAs/SM on 148 SMs -> always co-resident)
static constexpr int NBLK = 296;
static constexpr int NTHR = 256;
static constexpr int GSTR = NBLK * NTHR;   // 75776
static constexpr int H_TOTAL = NN * 32;    // h2half work units (uint2 each)
static constexpr int H_SPLIT = 1000000;    // units done in phase 3

// ---------------- scratch (__device__ globals; no allocs allowed) ------------
__device__ __half g_axh[(size_t)NN * 128]; // nin-scaled layer1 aggregate, fp16 (GEMM A)
__device__ __half g_y2h[(size_t)NN * 64];  // (relu(h1)*nout) @ W2, fp16
__device__ __half g_hx [(size_t)NN * 128]; // h * nout, fp16 (layer1 gather source)
__device__ int    g_odeg[NN];
__device__ int    g_ideg[NN];
__device__ float  g_nout[NN];
__device__ float  g_nin [NN];
__device__ int    g_off [NN + 1];
__device__ int    g_cur [NN];
__device__ int    g_bucket[NE];
__device__ int    g_part[SCAN_T];
__device__ int    g_pref[SCAN_T];

// software grid barrier state (self-cleaning across graph replays)
__device__ unsigned g_cnt   = 0;
__device__ unsigned g_phase = 0;   // monotone across barriers/replays

__device__ __forceinline__ void gbar() {
    __syncthreads();
    if (threadIdx.x == 0) {
        unsigned ph = *((volatile unsigned*)&g_phase);
        __threadfence();
        unsigned arrived = atomicAdd(&g_cnt, 1);
        if (arrived == NBLK - 1) {            // last CTA
            atomicExch(&g_cnt, 0);            // reset BEFORE releasing
            __threadfence();
            atomicAdd(&g_phase, 1);
        } else {
            while (*((volatile unsigned*)&g_phase) == ph) __nanosleep(64);
        }
        __threadfence();
    }
    __syncthreads();
}

__device__ __forceinline__ void h2half_unit(const float4* __restrict__ h4,
                                            uint2* __restrict__ o, int i) {
    int row = i >> 5;
    float s = g_nout[row];
    float4 v = h4[i];
    __half2 a = __floats2half2_rn(v.x * s, v.y * s);
    __half2 b = __floats2half2_rn(v.z * s, v.w * s);
    uint2 pkd;
    pkd.x = *reinterpret_cast<unsigned*>(&a);
    pkd.y = *reinterpret_cast<unsigned*>(&b);
    o[i] = pkd;
}

// ================= persistent preprocessing kernel ============================
// P0 zero degrees | P1 degree atomics | P2 norms+partials |
// P3 CTA0: scan partials, others: h2half[0,H_SPLIT) |
// P4 gid<1024: offsets, CTAs>=4: h2half[H_SPLIT,end) | P5 scatter
__global__ void __launch_bounds__(NTHR, 2)
prep_k(const int* __restrict__ src, const int* __restrict__ dst,
       const float* __restrict__ h) {
    const int gid = blockIdx.x * NTHR + threadIdx.x;
    const float4* h4 = reinterpret_cast<const float4*>(h);
    uint2* hx_out = reinterpret_cast<uint2*>(g_hx);

    // ---- P0: zero degree arrays ----
    for (int i = gid; i < NN; i += GSTR) { g_odeg[i] = 0; g_ideg[i] = 0; }
    gbar();

    // ---- P1: degree atomics (int4 edge reads) ----
    {
        const int4* s4 = reinterpret_cast<const int4*>(src);
        const int4* d4 = reinterpret_cast<const int4*>(dst);
        for (int i = gid; i < NE / 4; i += GSTR) {
            int4 s = s4[i];
            int4 d = d4[i];
            atomicAdd(&g_odeg[s.x], 1);
            atomicAdd(&g_odeg[s.y], 1);
            atomicAdd(&g_odeg[s.z], 1);
            atomicAdd(&g_odeg[s.w], 1);
            atomicAdd(&g_ideg[d.x], 1);
            atomicAdd(&g_ideg[d.y], 1);
            atomicAdd(&g_ideg[d.z], 1);
            atomicAdd(&g_ideg[d.w], 1);
        }
    }
    gbar();

    // ---- P2: norms + per-chunk partial sums ----
    for (int i = gid; i < NN; i += GSTR) {
        int od = g_odeg[i]; if (od < 1) od = 1;
        int id = g_ideg[i]; if (id < 1) id = 1;
        g_nout[i] = rsqrtf((float)od);
        g_nin[i]  = rsqrtf((float)id);
    }
    if (gid < SCAN_T) {
        int begin = gid * CHUNK;
        int endi  = begin + CHUNK; if (endi > NN) endi = NN;
        int sum = 0;
        if (begin < NN) {
            const int4* p = reinterpret_cast<const int4*>(g_ideg);
            #pragma unroll 13
            for (int i = begin / 4; i < endi / 4; i++) {
                int4 v = p[i];
                sum += v.x + v.y + v.z + v.w;
            }
        }
        g_part[gid] = sum;
    }
    gbar();

    // ---- P3: CTA0 scans partials; other CTAs run h2half part A ----
    if (blockIdx.x == 0) {
        __shared__ int wsum[8];
        int t = threadIdx.x;            // 256 threads x 4 partials each
        int4 p = reinterpret_cast<const int4*>(g_part)[t];
        int local = p.x + p.y + p.z + p.w;
        int lane = t & 31, wrp = t >> 5;
        int v = local;
        #pragma unroll
        for (int d = 1; d < 32; d <<= 1) {
            int n = __shfl_up_sync(0xffffffffu, v, d);
            if (lane >= d) v += n;
        }
        if (lane == 31) wsum[wrp] = v;
        __syncthreads();
        if (wrp == 0 && lane < 8) {
            int w = wsum[lane];
            #pragma unroll
            for (int d = 1; d < 8; d <<= 1) {
                int n = __shfl_up_sync(0xffu, w, d);
                if (lane >= d) w += n;
            }
            wsum[lane] = w;
        }
        __syncthreads();
        int excl = v - local + (wrp > 0 ? wsum[wrp - 1] : 0);
        g_pref[t * 4 + 0] = excl;
        g_pref[t * 4 + 1] = excl + p.x;
        g_pref[t * 4 + 2] = excl + p.x + p.y;
        g_pref[t * 4 + 3] = excl + p.x + p.y + p.z;
    } else {
        int i0 = (blockIdx.x - 1) * NTHR + threadIdx.x;
        int stridev = (NBLK - 1) * NTHR;
        for (int i = i0; i < H_SPLIT; i += stridev) h2half_unit(h4, hx_out, i);
    }
    gbar();

    // ---- P4: offsets replay (first 1024 threads) + h2half part B ----
    if (gid < SCAN_T) {
        int begin = gid * CHUNK;
        int endi  = begin + CHUNK; if (endi > NN) endi = NN;
        int running = g_pref[gid];
        for (int i = begin; i < endi; i++) {
            g_off[i] = running;
            g_cur[i] = running;
            running += g_ideg[i];
        }
        if (gid == SCAN_T - 1) g_off[NN] = NE;
    }
    if (blockIdx.x >= 4) {
        int i0 = (blockIdx.x - 4) * NTHR + threadIdx.x + H_SPLIT;
        int stridev = (NBLK - 4) * NTHR;
        for (int i = i0; i < H_TOTAL; i += stridev) h2half_unit(h4, hx_out, i);
    }
    gbar();

    // ---- P5: scatter (counting-sort by dst) ----
    {
        const int4* s4 = reinterpret_cast<const int4*>(src);
        const int4* d4 = reinterpret_cast<const int4*>(dst);
        for (int i = gid; i < NE / 4; i += GSTR) {
            int4 s = s4[i];
            int4 d = d4[i];
            g_bucket[atomicAdd(&g_cur[d.x], 1)] = s.x;
            g_bucket[atomicAdd(&g_cur[d.y], 1)] = s.y;
            g_bucket[atomicAdd(&g_cur[d.z], 1)] = s.z;
            g_bucket[atomicAdd(&g_cur[d.w], 1)] = s.w;
        }
    }
}

// ---------------- layer-1 SpMM as fp16 gather -> fp16 A ------------------------
__global__ void spmm1g_k() {
    unsigned w = (blockIdx.x * blockDim.x + threadIdx.x) >> 5;
    if (w >= NN) return;
    int lane = threadIdx.x & 31;
    int beg = g_off[w];
    int end = g_off[w + 1];
    const uint2* hx = reinterpret_cast<const uint2*>(g_hx);

    float4 acc = make_float4(0.f, 0.f, 0.f, 0.f);
    int e = beg;
    for (; e + 3 < end; e += 4) {
        int s0 = __ldg(&g_bucket[e]);
        int s1 = __ldg(&g_bucket[e + 1]);
        int s2 = __ldg(&g_bucket[e + 2]);
        int s3 = __ldg(&g_bucket[e + 3]);
        uint2 p0 = hx[(size_t)s0 * 32 + lane];
        uint2 p1 = hx[(size_t)s1 * 32 + lane];
        uint2 p2 = hx[(size_t)s2 * 32 + lane];
        uint2 p3 = hx[(size_t)s3 * 32 + lane];
        float2 a0 = __half22float2(*reinterpret_cast<__half2*>(&p0.x));
        float2 b0 = __half22float2(*reinterpret_cast<__half2*>(&p0.y));
        float2 a1 = __half22float2(*reinterpret_cast<__half2*>(&p1.x));
        float2 b1 = __half22float2(*reinterpret_cast<__half2*>(&p1.y));
        float2 a2 = __half22float2(*reinterpret_cast<__half2*>(&p2.x));
        float2 b2 = __half22float2(*reinterpret_cast<__half2*>(&p2.y));
        float2 a3 = __half22float2(*reinterpret_cast<__half2*>(&p3.x));
        float2 b3 = __half22float2(*reinterpret_cast<__half2*>(&p3.y));
        acc.x += (a0.x + a1.x) + (a2.x + a3.x);
        acc.y += (a0.y + a1.y) + (a2.y + a3.y);
        acc.z += (b0.x + b1.x) + (b2.x + b3.x);
        acc.w += (b0.y + b1.y) + (b2.y + b3.y);
    }
    for (; e < end; e++) {
        int s0 = __ldg(&g_bucket[e]);
        uint2 p0 = hx[(size_t)s0 * 32 + lane];
        float2 a0 = __half22float2(*reinterpret_cast<__half2*>(&p0.x));
        float2 b0 = __half22float2(*reinterpret_cast<__half2*>(&p0.y));
        acc.x += a0.x;  acc.y += a0.y;
        acc.z += b0.x;  acc.w += b0.y;
    }
    float ni = g_nin[w];
    __half2 h0 = __floats2half2_rn(acc.x * ni, acc.y * ni);
    __half2 h1 = __floats2half2_rn(acc.z * ni, acc.w * ni);
    uint2 pkd;
    pkd.x = *reinterpret_cast<unsigned*>(&h0);
    pkd.y = *reinterpret_cast<unsigned*>(&h1);
    reinterpret_cast<uint2*>(g_axh)[(size_t)w * 32 + lane] = pkd;
}

// ---------------- layer-2 SpMM as fp16 gather + fused epilogue -----------------
__global__ void spmm2g_k(const float* __restrict__ b2, float* __restrict__ out) {
    unsigned w = (blockIdx.x * blockDim.x + threadIdx.x) >> 5;
    if (w >= NN) return;
    int lane = threadIdx.x & 31;
    int beg = g_off[w];
    int end = g_off[w + 1];
    const unsigned* y2 = reinterpret_cast<const unsigned*>(g_y2h);

    float2 acc = make_float2(0.f, 0.f);
    int e = beg;
    for (; e + 3 < end; e += 4) {
        int s0 = __ldg(&g_bucket[e]);
        int s1 = __ldg(&g_bucket[e + 1]);
        int s2 = __ldg(&g_bucket[e + 2]);
        int s3 = __ldg(&g_bucket[e + 3]);
        unsigned p0 = y2[(size_t)s0 * 32 + lane];
        unsigned p1 = y2[(size_t)s1 * 32 + lane];
        unsigned p2 = y2[(size_t)s2 * 32 + lane];
        unsigned p3 = y2[(size_t)s3 * 32 + lane];
        float2 v0 = __half22float2(*reinterpret_cast<__half2*>(&p0));
        float2 v1 = __half22float2(*reinterpret_cast<__half2*>(&p1));
        float2 v2 = __half22float2(*reinterpret_cast<__half2*>(&p2));
        float2 v3 = __half22float2(*reinterpret_cast<__half2*>(&p3));
        acc.x += (v0.x + v1.x) + (v2.x + v3.x);
        acc.y += (v0.y + v1.y) + (v2.y + v3.y);
    }
    for (; e < end; e++) {
        int s0 = __ldg(&g_bucket[e]);
        unsigned p0 = y2[(size_t)s0 * 32 + lane];
        float2 v0 = __half22float2(*reinterpret_cast<__half2*>(&p0));
        acc.x += v0.x;
        acc.y += v0.y;
    }
    float ni = g_nin[w];
    float2 bb = reinterpret_cast<const float2*>(b2)[lane];
    float2 o;
    o.x = fmaxf(fmaf(acc.x, ni, bb.x), 0.f);
    o.y = fmaxf(fmaf(acc.y, ni, bb.y), 0.f);
    reinterpret_cast<float2*>(out)[(size_t)w * 32 + lane] = o;
}

// ================= wmma (HMMA) fused double-GEMM ==============================
static constexpr int LDA  = 136;   // halves, padded
static constexpr int LDW2 = 72;    // halves
static constexpr int LDC  = 132;   // floats

static constexpr int OFF_A  = 0;
static constexpr int OFF_W1 = OFF_A  + 128 * LDA * 2;
static constexpr int OFF_W2 = OFF_W1 + 128 * LDA * 2;
static constexpr int OFF_C  = OFF_W2 + 128 * LDW2 * 2;
static constexpr int OFF_B1 = OFF_C  + 128 * LDC * 4;
static constexpr int WMMA_SMEM = OFF_B1 + 512;

__global__ void __launch_bounds__(256, 1)
fused_mlp_wmma(const float* __restrict__ W1, const float* __restrict__ b1,
               const float* __restrict__ W2) {
    extern __shared__ char smem[];
    __half* sA  = reinterpret_cast<__half*>(smem + OFF_A);
    __half* sW1 = reinterpret_cast<__half*>(smem + OFF_W1);
    __half* sW2 = reinterpret_cast<__half*>(smem + OFF_W2);
    float*  sC  = reinterpret_cast<float*>(smem + OFF_C);
    float*  sb1 = reinterpret_cast<float*>(smem + OFF_B1);
    const int tid  = threadIdx.x;
    const int wid  = tid >> 5;
    const int row0 = blockIdx.x * 128;

    if (tid < 128) sb1[tid] = b1[tid];

    {
        int m = tid >> 1;
        int q = tid & 1;
        int r = row0 + m;
        const uint4* ar = reinterpret_cast<const uint4*>(
            g_axh + (size_t)(r < NN ? r : 0) * 128);
        uint4* dstp = reinterpret_cast<uint4*>(sA + m * LDA + q * 64);
        #pragma unroll
        for (int j = 0; j < 8; j++) {
            uint4 v = (r < NN) ? ar[q * 8 + j] : make_uint4(0u, 0u, 0u, 0u);
            dstp[j] = v;
        }
    }
    for (int idx = tid; idx < 128 * 64; idx += 256) {
        int k = idx >> 6;
        int n2 = (idx & 63) * 2;
        __half2 hh = __floats2half2_rn(W1[k * 128 + n2], W1[k * 128 + n2 + 1]);
        *reinterpret_cast<__half2*>(sW1 + k * LDA + n2) = hh;
    }
    for (int idx = tid; idx < 128 * 32; idx += 256) {
        int k = idx >> 5;
        int n2 = (idx & 31) * 2;
        __half2 hh = __floats2half2_rn(W2[k * 64 + n2], W2[k * 64 + n2 + 1]);
        *reinterpret_cast<__half2*>(sW2 + k * LDW2 + n2) = hh;
    }
    __syncthreads();

    {
        const int m0 = wid * 16;
        #pragma unroll
        for (int n0 = 0; n0 < 128; n0 += 16) {
            wmma::fragment<wmma::accumulator, 16, 16, 16, float> c;
            wmma::fill_fragment(c, 0.0f);
            #pragma unroll
            for (int k0 = 0; k0 < 128; k0 += 16) {
                wmma::fragment<wmma::matrix_a, 16, 16, 16, __half, wmma::row_major> a;
                wmma::fragment<wmma::matrix_b, 16, 16, 16, __half, wmma::row_major> b;
                wmma::load_matrix_sync(a, sA + m0 * LDA + k0, LDA);
                wmma::load_matrix_sync(b, sW1 + k0 * LDA + n0, LDA);
                wmma::mma_sync(c, a, b, c);
            }
            wmma::store_matrix_sync(sC + m0 * LDC + n0, c, LDC, wmma::mem_row_major);
        }
    }
    __syncthreads();

    for (int idx = tid; idx < 128 * 64; idx += 256) {
        int m = idx >> 6;
        int c2 = (idx & 63) * 2;
        int r = row0 + m;
        float no = (r < NN) ? g_nout[r] : 0.f;
        float v0 = fmaxf(sC[m * LDC + c2]     + sb1[c2],     0.f) * no;
        float v1 = fmaxf(sC[m * LDC + c2 + 1] + sb1[c2 + 1], 0.f) * no;
        *reinterpret_cast<__half2*>(sA + m * LDA + c2) = __floats2half2_rn(v0, v1);
    }
    __syncthreads();

    {
        const int m0 = wid * 16;
        #pragma unroll
        for (int n0 = 0; n0 < 64; n0 += 16) {
            wmma::fragment<wmma::accumulator, 16, 16, 16, float> c;
            wmma::fill_fragment(c, 0.0f);
            #pragma unroll
            for (int k0 = 0; k0 < 128; k0 += 16) {
                wmma::fragment<wmma::matrix_a, 16, 16, 16, __half, wmma::row_major> a;
                wmma::fragment<wmma::matrix_b, 16, 16, 16, __half, wmma::row_major> b;
                wmma::load_matrix_sync(a, sA + m0 * LDA + k0, LDA);
                wmma::load_matrix_sync(b, sW2 + k0 * LDW2 + n0, LDW2);
                wmma::mma_sync(c, a, b, c);
            }
            wmma::store_matrix_sync(sC + m0 * LDC + n0, c, LDC, wmma::mem_row_major);
        }
    }
    __syncthreads();

    for (int idx = tid; idx < 128 * 32; idx += 256) {
        int m = idx >> 5;
        int c2 = (idx & 31) * 2;
        int r = row0 + m;
        if (r < NN) {
            __half2 hh = __floats2half2_rn(sC[m * LDC + c2], sC[m * LDC + c2 + 1]);
            *reinterpret_cast<__half2*>(g_y2h + (size_t)r * 64 + c2) = hh;
        }
    }
}

// ---------------- launch ------------------------------------------------------

extern "C" void kernel_launch(void* const* d_in, const int* in_sizes, int n_in,
                              void* d_out, int out_size) {
    const float* h  = (const float*)d_in[0];
    const float* W1 = (const float*)d_in[1];
    const float* b1 = (const float*)d_in[2];
    const float* W2 = (const float*)d_in[3];
    const float* b2 = (const float*)d_in[4];
    const int*   src = (const int*)d_in[5];
    const int*   dst = (const int*)d_in[6];
    float* out = (float*)d_out;
    (void)in_sizes; (void)n_in; (void)out_size;

    cudaFuncSetAttribute(fused_mlp_wmma,
                         cudaFuncAttributeMaxDynamicSharedMemorySize, WMMA_SMEM);

    prep_k<<<NBLK, NTHR>>>(src, dst, h);                     // all preprocessing
    spmm1g_k<<<(NN * 32 + 255) / 256, 256>>>();              // 1 warp/node
    fused_mlp_wmma<<<(NN + 127) / 128, 256, WMMA_SMEM>>>(W1, b1, W2);
    spmm2g_k<<<(NN * 32 + 255) / 256, 256>>>(b2, out);       // 1 warp/node
}

// round 16
// speedup vs baseline: 1.1485x; 1.1485x over previous
#include <cuda_runtime.h>
#include <cuda_fp16.h>
#include <mma.h>
#include <cstdint>

using namespace nvcuda;

// Problem constants (fixed by the dataset)
static constexpr int NN = 50000;   // nodes
static constexpr int NE = 800000;  // edges (divisible by 4)
// features: 128 -> 128 (hidden) -> 64 (out)

// scan decomposition
static constexpr int SCAN_T = 1024;
static constexpr int CHUNK  = 52;          // 1024*52 = 53248 >= NN

// ---------------- scratch (__device__ globals; no allocs allowed) ------------
__device__ __half g_axh[(size_t)NN * 128]; // nin-scaled layer1 aggregate, fp16 (GEMM A)
__device__ __half g_y2h[(size_t)NN * 64];  // (relu(h1)*nout) @ W2, fp16
__device__ __half g_hx [(size_t)NN * 128]; // h * nout, fp16 (layer1 gather source)
__device__ int    g_odeg[NN];
__device__ int    g_ideg[NN];
__device__ float  g_nout[NN];
__device__ float  g_nin [NN];
__device__ int    g_off [NN + 1];
__device__ int    g_cur [NN];
__device__ int    g_bucket[NE];
__device__ int    g_part[SCAN_T];
__device__ int    g_pref[SCAN_T];

__device__ __forceinline__ __half2 u2h(unsigned u) {
    return *reinterpret_cast<__half2*>(&u);
}

// ---------------- graph preprocessing ----------------------------------------

__global__ void degree_k(const int* __restrict__ src, const int* __restrict__ dst) {
    int i0 = blockIdx.x * blockDim.x + threadIdx.x;
    int stride = gridDim.x * blockDim.x;
    const int4* s4 = reinterpret_cast<const int4*>(src);
    const int4* d4 = reinterpret_cast<const int4*>(dst);
    for (int i = i0; i < NE / 4; i += stride) {
        int4 s = s4[i];
        int4 d = d4[i];
        atomicAdd(&g_odeg[s.x], 1);
        atomicAdd(&g_odeg[s.y], 1);
        atomicAdd(&g_odeg[s.z], 1);
        atomicAdd(&g_odeg[s.w], 1);
        atomicAdd(&g_ideg[d.x], 1);
        atomicAdd(&g_ideg[d.y], 1);
        atomicAdd(&g_ideg[d.z], 1);
        atomicAdd(&g_ideg[d.w], 1);
    }
}

__global__ void norm_partial_k() {
    int gid = blockIdx.x * blockDim.x + threadIdx.x;
    int stride = gridDim.x * blockDim.x;
    for (int i = gid; i < NN; i += stride) {
        int od = g_odeg[i]; if (od < 1) od = 1;
        int id = g_ideg[i]; if (id < 1) id = 1;
        g_nout[i] = rsqrtf((float)od);
        g_nin[i]  = rsqrtf((float)id);
    }
    if (gid < SCAN_T) {
        int begin = gid * CHUNK;
        int endi  = begin + CHUNK; if (endi > NN) endi = NN;
        int sum = 0;
        if (begin < NN) {
            const int4* p = reinterpret_cast<const int4*>(g_ideg);
            #pragma unroll 13
            for (int i = begin / 4; i < endi / 4; i++) {
                int4 v = p[i];
                sum += v.x + v.y + v.z + v.w;
            }
        }
        g_part[gid] = sum;
    }
}

__global__ void __launch_bounds__(SCAN_T, 1) scanpart_k() {
    __shared__ int wsum[32];
    int t    = threadIdx.x;
    int lane = t & 31;
    int wid  = t >> 5;

    int own = g_part[t];
    int v = own;
    #pragma unroll
    for (int d = 1; d < 32; d <<= 1) {
        int n = __shfl_up_sync(0xffffffffu, v, d);
        if (lane >= d) v += n;
    }
    if (lane == 31) wsum[wid] = v;
    __syncthreads();
    if (wid == 0) {
        int w = wsum[lane];
        #pragma unroll
        for (int d = 1; d < 32; d <<= 1) {
            int n = __shfl_up_sync(0xffffffffu, w, d);
            if (lane >= d) w += n;
        }
        wsum[lane] = w;
    }
    __syncthreads();

    g_pref[t] = v - own + (wid > 0 ? wsum[wid - 1] : 0);
}

__global__ void offsets_k() {
    int t = blockIdx.x * blockDim.x + threadIdx.x;
    if (t >= SCAN_T) return;
    int begin = t * CHUNK;
    int endi  = begin + CHUNK; if (endi > NN) endi = NN;
    int running = g_pref[t];
    for (int i = begin; i < endi; i++) {
        g_off[i] = running;
        g_cur[i] = running;
        running += g_ideg[i];
    }
    if (t == SCAN_T - 1) g_off[NN] = NE;
}

__global__ void scatter_k(const int* __restrict__ src, const int* __restrict__ dst) {
    int i0 = blockIdx.x * blockDim.x + threadIdx.x;
    int stride = gridDim.x * blockDim.x;
    const int4* s4 = reinterpret_cast<const int4*>(src);
    const int4* d4 = reinterpret_cast<const int4*>(dst);
    for (int i = i0; i < NE / 4; i += stride) {
        int4 s = s4[i];
        int4 d = d4[i];
        g_bucket[atomicAdd(&g_cur[d.x], 1)] = s.x;
        g_bucket[atomicAdd(&g_cur[d.y], 1)] = s.y;
        g_bucket[atomicAdd(&g_cur[d.z], 1)] = s.z;
        g_bucket[atomicAdd(&g_cur[d.w], 1)] = s.w;
    }
}

// ---------------- fp16 pre-scaled features ------------------------------------
__global__ void h2half_k(const float* __restrict__ h) {
    int i0 = blockIdx.x * blockDim.x + threadIdx.x;
    int stride = gridDim.x * blockDim.x;
    const float4* h4 = reinterpret_cast<const float4*>(h);
    uint2* o = reinterpret_cast<uint2*>(g_hx);
    for (int i = i0; i < NN * 32; i += stride) {
        int row = i >> 5;
        float s = g_nout[row];
        float4 v = h4[i];
        __half2 a = __floats2half2_rn(v.x * s, v.y * s);
        __half2 b = __floats2half2_rn(v.z * s, v.w * s);
        uint2 pkd;
        pkd.x = *reinterpret_cast<unsigned*>(&a);
        pkd.y = *reinterpret_cast<unsigned*>(&b);
        o[i] = pkd;
    }
}

// ---------------- layer-1 SpMM as fp16 gather -> fp16 A ------------------------
// 4-edge groups summed with HADD2 tree (fp16), then folded into fp32 acc.
__global__ void spmm1g_k() {
    unsigned w = (blockIdx.x * blockDim.x + threadIdx.x) >> 5;
    if (w >= NN) return;
    int lane = threadIdx.x & 31;
    int beg = g_off[w];
    int end = g_off[w + 1];
    const uint2* hx = reinterpret_cast<const uint2*>(g_hx);

    float4 acc = make_float4(0.f, 0.f, 0.f, 0.f);
    int e = beg;
    for (; e + 3 < end; e += 4) {
        int s0 = __ldg(&g_bucket[e]);
        int s1 = __ldg(&g_bucket[e + 1]);
        int s2 = __ldg(&g_bucket[e + 2]);
        int s3 = __ldg(&g_bucket[e + 3]);
        uint2 p0 = hx[(size_t)s0 * 32 + lane];
        uint2 p1 = hx[(size_t)s1 * 32 + lane];
        uint2 p2 = hx[(size_t)s2 * 32 + lane];
        uint2 p3 = hx[(size_t)s3 * 32 + lane];
        // fp16 tree over the 4-edge group (3 HADD2 per component pair)
        __half2 qx = __hadd2(__hadd2(u2h(p0.x), u2h(p1.x)),
                             __hadd2(u2h(p2.x), u2h(p3.x)));
        __half2 qy = __hadd2(__hadd2(u2h(p0.y), u2h(p1.y)),
                             __hadd2(u2h(p2.y), u2h(p3.y)));
        float2 fx = __half22float2(qx);
        float2 fy = __half22float2(qy);
        acc.x += fx.x;  acc.y += fx.y;
        acc.z += fy.x;  acc.w += fy.y;
    }
    for (; e < end; e++) {
        int s0 = __ldg(&g_bucket[e]);
        uint2 p0 = hx[(size_t)s0 * 32 + lane];
        float2 a0 = __half22float2(u2h(p0.x));
        float2 b0 = __half22float2(u2h(p0.y));
        acc.x += a0.x;  acc.y += a0.y;
        acc.z += b0.x;  acc.w += b0.y;
    }
    float ni = g_nin[w];
    __half2 h0 = __floats2half2_rn(acc.x * ni, acc.y * ni);
    __half2 h1 = __floats2half2_rn(acc.z * ni, acc.w * ni);
    uint2 pkd;
    pkd.x = *reinterpret_cast<unsigned*>(&h0);
    pkd.y = *reinterpret_cast<unsigned*>(&h1);
    reinterpret_cast<uint2*>(g_axh)[(size_t)w * 32 + lane] = pkd;
}

// ---------------- layer-2 SpMM as fp16 gather + fused epilogue -----------------
__global__ void spmm2g_k(const float* __restrict__ b2, float* __restrict__ out) {
    unsigned w = (blockIdx.x * blockDim.x + threadIdx.x) >> 5;
    if (w >= NN) return;
    int lane = threadIdx.x & 31;
    int beg = g_off[w];
    int end = g_off[w + 1];
    const unsigned* y2 = reinterpret_cast<const unsigned*>(g_y2h);

    float2 acc = make_float2(0.f, 0.f);
    int e = beg;
    for (; e + 3 < end; e += 4) {
        int s0 = __ldg(&g_bucket[e]);
        int s1 = __ldg(&g_bucket[e + 1]);
        int s2 = __ldg(&g_bucket[e + 2]);
        int s3 = __ldg(&g_bucket[e + 3]);
        unsigned p0 = y2[(size_t)s0 * 32 + lane];
        unsigned p1 = y2[(size_t)s1 * 32 + lane];
        unsigned p2 = y2[(size_t)s2 * 32 + lane];
        unsigned p3 = y2[(size_t)s3 * 32 + lane];
        __half2 q = __hadd2(__hadd2(u2h(p0), u2h(p1)),
                            __hadd2(u2h(p2), u2h(p3)));
        float2 v = __half22float2(q);
        acc.x += v.x;
        acc.y += v.y;
    }
    for (; e < end; e++) {
        int s0 = __ldg(&g_bucket[e]);
        unsigned p0 = y2[(size_t)s0 * 32 + lane];
        float2 v0 = __half22float2(u2h(p0));
        acc.x += v0.x;
        acc.y += v0.y;
    }
    float ni = g_nin[w];
    float2 bb = reinterpret_cast<const float2*>(b2)[lane];
    float2 o;
    o.x = fmaxf(fmaf(acc.x, ni, bb.x), 0.f);
    o.y = fmaxf(fmaf(acc.y, ni, bb.y), 0.f);
    reinterpret_cast<float2*>(out)[(size_t)w * 32 + lane] = o;
}

// ================= wmma (HMMA) fused double-GEMM ==============================
static constexpr int LDA  = 136;   // halves, padded
static constexpr int LDW2 = 72;    // halves
static constexpr int LDC  = 132;   // floats

static constexpr int OFF_A  = 0;
static constexpr int OFF_W1 = OFF_A  + 128 * LDA * 2;
static constexpr int OFF_W2 = OFF_W1 + 128 * LDA * 2;
static constexpr int OFF_C  = OFF_W2 + 128 * LDW2 * 2;
static constexpr int OFF_B1 = OFF_C  + 128 * LDC * 4;
static constexpr int WMMA_SMEM = OFF_B1 + 512;

__global__ void __launch_bounds__(256, 1)
fused_mlp_wmma(const float* __restrict__ W1, const float* __restrict__ b1,
               const float* __restrict__ W2) {
    extern __shared__ char smem[];
    __half* sA  = reinterpret_cast<__half*>(smem + OFF_A);
    __half* sW1 = reinterpret_cast<__half*>(smem + OFF_W1);
    __half* sW2 = reinterpret_cast<__half*>(smem + OFF_W2);
    float*  sC  = reinterpret_cast<float*>(smem + OFF_C);
    float*  sb1 = reinterpret_cast<float*>(smem + OFF_B1);
    const int tid  = threadIdx.x;
    const int wid  = tid >> 5;
    const int row0 = blockIdx.x * 128;

    if (tid < 128) sb1[tid] = b1[tid];

    {
        int m = tid >> 1;
        int q = tid & 1;
        int r = row0 + m;
        const uint4* ar = reinterpret_cast<const uint4*>(
            g_axh + (size_t)(r < NN ? r : 0) * 128);
        uint4* dstp = reinterpret_cast<uint4*>(sA + m * LDA + q * 64);
        #pragma unroll
        for (int j = 0; j < 8; j++) {
            uint4 v = (r < NN) ? ar[q * 8 + j] : make_uint4(0u, 0u, 0u, 0u);
            dstp[j] = v;
        }
    }
    for (int idx = tid; idx < 128 * 64; idx += 256) {
        int k = idx >> 6;
        int n2 = (idx & 63) * 2;
        __half2 hh = __floats2half2_rn(W1[k * 128 + n2], W1[k * 128 + n2 + 1]);
        *reinterpret_cast<__half2*>(sW1 + k * LDA + n2) = hh;
    }
    for (int idx = tid; idx < 128 * 32; idx += 256) {
        int k = idx >> 5;
        int n2 = (idx & 31) * 2;
        __half2 hh = __floats2half2_rn(W2[k * 64 + n2], W2[k * 64 + n2 + 1]);
        *reinterpret_cast<__half2*>(sW2 + k * LDW2 + n2) = hh;
    }
    __syncthreads();

    {
        const int m0 = wid * 16;
        #pragma unroll
        for (int n0 = 0; n0 < 128; n0 += 16) {
            wmma::fragment<wmma::accumulator, 16, 16, 16, float> c;
            wmma::fill_fragment(c, 0.0f);
            #pragma unroll
            for (int k0 = 0; k0 < 128; k0 += 16) {
                wmma::fragment<wmma::matrix_a, 16, 16, 16, __half, wmma::row_major> a;
                wmma::fragment<wmma::matrix_b, 16, 16, 16, __half, wmma::row_major> b;
                wmma::load_matrix_sync(a, sA + m0 * LDA + k0, LDA);
                wmma::load_matrix_sync(b, sW1 + k0 * LDA + n0, LDA);
                wmma::mma_sync(c, a, b, c);
            }
            wmma::store_matrix_sync(sC + m0 * LDC + n0, c, LDC, wmma::mem_row_major);
        }
    }
    __syncthreads();

    for (int idx = tid; idx < 128 * 64; idx += 256) {
        int m = idx >> 6;
        int c2 = (idx & 63) * 2;
        int r = row0 + m;
        float no = (r < NN) ? g_nout[r] : 0.f;
        float v0 = fmaxf(sC[m * LDC + c2]     + sb1[c2],     0.f) * no;
        float v1 = fmaxf(sC[m * LDC + c2 + 1] + sb1[c2 + 1], 0.f) * no;
        *reinterpret_cast<__half2*>(sA + m * LDA + c2) = __floats2half2_rn(v0, v1);
    }
    __syncthreads();

    {
        const int m0 = wid * 16;
        #pragma unroll
        for (int n0 = 0; n0 < 64; n0 += 16) {
            wmma::fragment<wmma::accumulator, 16, 16, 16, float> c;
            wmma::fill_fragment(c, 0.0f);
            #pragma unroll
            for (int k0 = 0; k0 < 128; k0 += 16) {
                wmma::fragment<wmma::matrix_a, 16, 16, 16, __half, wmma::row_major> a;
                wmma::fragment<wmma::matrix_b, 16, 16, 16, __half, wmma::row_major> b;
                wmma::load_matrix_sync(a, sA + m0 * LDA + k0, LDA);
                wmma::load_matrix_sync(b, sW2 + k0 * LDW2 + n0, LDW2);
                wmma::mma_sync(c, a, b, c);
            }
            wmma::store_matrix_sync(sC + m0 * LDC + n0, c, LDC, wmma::mem_row_major);
        }
    }
    __syncthreads();

    for (int idx = tid; idx < 128 * 32; idx += 256) {
        int m = idx >> 5;
        int c2 = (idx & 31) * 2;
        int r = row0 + m;
        if (r < NN) {
            __half2 hh = __floats2half2_rn(sC[m * LDC + c2], sC[m * LDC + c2 + 1]);
            *reinterpret_cast<__half2*>(g_y2h + (size_t)r * 64 + c2) = hh;
        }
    }
}

// ---------------- launch ------------------------------------------------------

extern "C" void kernel_launch(void* const* d_in, const int* in_sizes, int n_in,
                              void* d_out, int out_size) {
    const float* h  = (const float*)d_in[0];
    const float* W1 = (const float*)d_in[1];
    const float* b1 = (const float*)d_in[2];
    const float* W2 = (const float*)d_in[3];
    const float* b2 = (const float*)d_in[4];
    const int*   src = (const int*)d_in[5];
    const int*   dst = (const int*)d_in[6];
    float* out = (float*)d_out;
    (void)in_sizes; (void)n_in; (void)out_size;

    cudaFuncSetAttribute(fused_mlp_wmma,
                         cudaFuncAttributeMaxDynamicSharedMemorySize, WMMA_SMEM);

    // side stream + events for overlapping h2half with the CSR build
    static cudaStream_t s2 = nullptr;
    static cudaEvent_t evFork = nullptr, evJoin = nullptr;
    if (s2 == nullptr) {
        cudaStreamCreateWithFlags(&s2, cudaStreamNonBlocking);
        cudaEventCreateWithFlags(&evFork, cudaEventDisableTiming);
        cudaEventCreateWithFlags(&evJoin, cudaEventDisableTiming);
    }

    void* odeg_p = nullptr; void* ideg_p = nullptr;
    cudaGetSymbolAddress(&odeg_p, g_odeg);
    cudaGetSymbolAddress(&ideg_p, g_ideg);
    cudaMemsetAsync(odeg_p, 0, NN * sizeof(int));
    cudaMemsetAsync(ideg_p, 0, NN * sizeof(int));

    degree_k<<<512, 256>>>(src, dst);
    norm_partial_k<<<98, 512>>>();

    // fork: h2half depends only on norms; overlap with scan/offsets/scatter
    cudaEventRecord(evFork, 0);
    cudaStreamWaitEvent(s2, evFork, 0);
    h2half_k<<<1024, 256, 0, s2>>>(h);
    cudaEventRecord(evJoin, s2);

    scanpart_k<<<1, SCAN_T>>>();
    offsets_k<<<8, 128>>>();
    scatter_k<<<512, 256>>>(src, dst);

    cudaStreamWaitEvent(0, evJoin, 0);   // join before the gather reads g_hx

    spmm1g_k<<<(NN * 32 + 255) / 256, 256>>>();              // 1 warp/node
    fused_mlp_wmma<<<(NN + 127) / 128, 256, WMMA_SMEM>>>(W1, b1, W2);
    spmm2g_k<<<(NN * 32 + 255) / 256, 256>>>(b2, out);       // 1 warp/node
}